// round 2
// baseline (speedup 1.0000x reference)
#include <cuda_runtime.h>

#define LL   128
#define NB   32
#define CC   128
#define MM   128   // dim_mlp
#define OO   128   // out
#define NR   (LL*NB)   // 4096 rows

// Scratch (device globals: no allocation allowed)
__device__ float g_A [NR*MM];        // A[r][m],  r = i*NB+b
__device__ float g_Bt[NB*MM*LL];     // Bt[b][m][j]
__device__ float g_HV[NR*MM];        // relu(x@Vw1+vb1)
__device__ float g_V [NR*OO];        // value[r][c]

// ---------------------------------------------------------------------------
// prep1: A = X@W1_top ; B = X@W1_bot + b1 (stored transposed per-b) ;
//        HV = relu(X@Vw1 + vb1)
// grid 256 blocks x 256 threads, 16 rows per block
// ---------------------------------------------------------------------------
__global__ __launch_bounds__(256) void prep1(
    const float* __restrict__ X,  const float* __restrict__ W1,
    const float* __restrict__ b1, const float* __restrict__ Vw1,
    const float* __restrict__ vb1)
{
    __shared__ float xs[16*128];
    const int r0  = blockIdx.x * 16;
    const int tid = threadIdx.x;

    for (int idx = tid; idx < 16*128/4; idx += 256)
        ((float4*)xs)[idx] = ((const float4*)(X + r0*128))[idx];
    __syncthreads();

    const int rl = tid >> 4;            // row in block 0..15
    const int m0 = (tid & 15) * 8;      // output col group
    const int r  = r0 + rl;

    float a[8], bb[8], hv[8];
    #pragma unroll
    for (int q = 0; q < 8; q++) {
        a[q]  = 0.f;
        bb[q] = b1 [m0 + q];
        hv[q] = vb1[m0 + q];
    }

    for (int c = 0; c < 128; c++) {
        const float xv = xs[rl*128 + c];
        float wt[8], wb[8], wv[8];
        *(float4*)&wt[0] = *(const float4*)(W1  +        c*128 + m0);
        *(float4*)&wt[4] = *(const float4*)(W1  +        c*128 + m0 + 4);
        *(float4*)&wb[0] = *(const float4*)(W1  + (128 + c)*128 + m0);
        *(float4*)&wb[4] = *(const float4*)(W1  + (128 + c)*128 + m0 + 4);
        *(float4*)&wv[0] = *(const float4*)(Vw1 +        c*128 + m0);
        *(float4*)&wv[4] = *(const float4*)(Vw1 +        c*128 + m0 + 4);
        #pragma unroll
        for (int q = 0; q < 8; q++) {
            a [q] += xv * wt[q];
            bb[q] += xv * wb[q];
            hv[q] += xv * wv[q];
        }
    }

    const int j = r >> 5;      // r = i*32+b : key index for B rows
    const int b = r & 31;
    #pragma unroll
    for (int q = 0; q < 8; q++) {
        g_A [r*128 + m0 + q]            = a[q];
        g_Bt[b*(MM*LL) + (m0+q)*LL + j] = bb[q];
        g_HV[r*128 + m0 + q]            = fmaxf(hv[q], 0.f);
    }
}

// ---------------------------------------------------------------------------
// prep2: V = HV @ Vw2 + vb2
// ---------------------------------------------------------------------------
__global__ __launch_bounds__(256) void prep2(
    const float* __restrict__ Vw2, const float* __restrict__ vb2)
{
    __shared__ float xs[16*128];
    const int r0  = blockIdx.x * 16;
    const int tid = threadIdx.x;

    for (int idx = tid; idx < 16*128/4; idx += 256)
        ((float4*)xs)[idx] = ((const float4*)(g_HV + r0*128))[idx];
    __syncthreads();

    const int rl = tid >> 4;
    const int m0 = (tid & 15) * 8;
    const int r  = r0 + rl;

    float v[8];
    #pragma unroll
    for (int q = 0; q < 8; q++) v[q] = vb2[m0 + q];

    for (int c = 0; c < 128; c++) {
        const float xv = xs[rl*128 + c];
        float w[8];
        *(float4*)&w[0] = *(const float4*)(Vw2 + c*128 + m0);
        *(float4*)&w[4] = *(const float4*)(Vw2 + c*128 + m0 + 4);
        #pragma unroll
        for (int q = 0; q < 8; q++) v[q] += xv * w[q];
    }
    #pragma unroll
    for (int q = 0; q < 8; q++) g_V[r*128 + m0 + q] = v[q];
}

// ---------------------------------------------------------------------------
// main: per (b, i-tile of 16):
//   for each i: M = relu(A_i + B_b) @ W2 ; out[i,b,c] = sum_j (M[j,c]+b2[c])*V[j,b,c]
// smem: Bt_b 64K + W2 64K + V_b 64K + A 8K + red 8K = 208 KB
// ---------------------------------------------------------------------------
#define SMEM_BYTES ((16384*3 + 2048 + 2048) * 4)

__global__ __launch_bounds__(256) void mainkern(
    const float* __restrict__ W2, const float* __restrict__ b2,
    float* __restrict__ outp)
{
    extern __shared__ float sm[];
    float* sBt  = sm;                 // [m][j]  16384
    float* sW2  = sm + 16384;         // [m][c]  16384
    float* sV   = sm + 32768;         // [j][c]  16384
    float* sA   = sm + 49152;         // [il][m]  2048
    float* sRed = sm + 51200;         // [tj][c]  2048

    const int b   = blockIdx.y;
    const int i0  = blockIdx.x * 16;
    const int tid = threadIdx.x;

    for (int idx = tid; idx < 4096; idx += 256) {
        ((float4*)sBt)[idx] = ((const float4*)(g_Bt + b*16384))[idx];
        ((float4*)sW2)[idx] = ((const float4*)W2)[idx];
    }
    for (int idx = tid; idx < 4096; idx += 256) {
        const int j  = idx >> 5;
        const int c4 = idx & 31;
        ((float4*)sV)[idx] = ((const float4*)(g_V + (j*NB + b)*128))[c4];
    }
    for (int idx = tid; idx < 512; idx += 256) {
        const int il = idx >> 5;
        const int m4 = idx & 31;
        ((float4*)sA)[idx] = ((const float4*)(g_A + ((i0+il)*NB + b)*128))[m4];
    }
    __syncthreads();

    const int tj = tid >> 4;        // 0..15 : j group
    const int tc = tid & 15;        // 0..15 : c group
    const int j0 = tj * 8;
    const int c0 = tc * 8;

    float b2f[8];
    *(float4*)&b2f[0] = *(const float4*)(b2 + c0);
    *(float4*)&b2f[4] = *(const float4*)(b2 + c0 + 4);

    for (int il = 0; il < 16; il++) {
        float acc[8][8];
        #pragma unroll
        for (int jj = 0; jj < 8; jj++)
            #pragma unroll
            for (int cc = 0; cc < 8; cc++) acc[jj][cc] = 0.f;

        const float* aRow = sA + il*128;

        #pragma unroll 4
        for (int m = 0; m < 128; m++) {
            const float am = aRow[m];
            float h[8], w[8];
            *(float4*)&h[0] = *(const float4*)&sBt[m*128 + j0];
            *(float4*)&h[4] = *(const float4*)&sBt[m*128 + j0 + 4];
            #pragma unroll
            for (int q = 0; q < 8; q++) h[q] = fmaxf(h[q] + am, 0.f);
            *(float4*)&w[0] = *(const float4*)&sW2[m*128 + c0];
            *(float4*)&w[4] = *(const float4*)&sW2[m*128 + c0 + 4];
            #pragma unroll
            for (int jj = 0; jj < 8; jj++)
                #pragma unroll
                for (int cc = 0; cc < 8; cc++)
                    acc[jj][cc] += h[jj] * w[cc];
        }

        // epilogue: value-weighted reduction over this thread's 8 j rows
        float s[8];
        #pragma unroll
        for (int cc = 0; cc < 8; cc++) s[cc] = 0.f;
        #pragma unroll
        for (int jj = 0; jj < 8; jj++) {
            float v[8];
            *(float4*)&v[0] = *(const float4*)&sV[(j0+jj)*128 + c0];
            *(float4*)&v[4] = *(const float4*)&sV[(j0+jj)*128 + c0 + 4];
            #pragma unroll
            for (int cc = 0; cc < 8; cc++)
                s[cc] += (acc[jj][cc] + b2f[cc]) * v[cc];
        }
        *(float4*)&sRed[tj*128 + c0]     = *(float4*)&s[0];
        *(float4*)&sRed[tj*128 + c0 + 4] = *(float4*)&s[4];
        __syncthreads();

        if (tid < 128) {
            float t = 0.f;
            #pragma unroll
            for (int g = 0; g < 16; g++) t += sRed[g*128 + tid];
            outp[((i0 + il)*NB + b)*128 + tid] = t;
        }
        __syncthreads();
    }
}

// ---------------------------------------------------------------------------
extern "C" void kernel_launch(void* const* d_in, const int* in_sizes, int n_in,
                              void* d_out, int out_size)
{
    const float* x   = (const float*)d_in[0];
    const float* aw1 = (const float*)d_in[1];
    const float* ab1 = (const float*)d_in[2];
    const float* aw2 = (const float*)d_in[3];
    const float* ab2 = (const float*)d_in[4];
    const float* vw1 = (const float*)d_in[5];
    const float* vb1 = (const float*)d_in[6];
    const float* vw2 = (const float*)d_in[7];
    const float* vb2 = (const float*)d_in[8];
    float* outp = (float*)d_out;

    cudaFuncSetAttribute(mainkern, cudaFuncAttributeMaxDynamicSharedMemorySize,
                         SMEM_BYTES);

    prep1<<<256, 256>>>(x, aw1, ab1, vw1, vb1);
    prep2<<<256, 256>>>(vw2, vb2);
    mainkern<<<dim3(8, 32), 256, SMEM_BYTES>>>(aw2, ab2, outp);
}